// round 16
// baseline (speedup 1.0000x reference)
#include <cuda_runtime.h>
#include <cuda_bf16.h>
#include <math.h>
#include <stdint.h>

// ---------------------------------------------------------------------------
// TreeLSTM on GB300, mma.sync bf16x3 (tcgen05 feature-gated off on this
// harness's compute_103 target).
// R16: R14 PDL semantics restored (programmatic stream serialization, NO
// explicit triggers -> implicit trigger at kernel completion keeps
// cudaGridDependencySynchronize a true producer-complete wait). R15's
// preambles are kept: loads of >=2-kernel-old data (weights, x, c_prev)
// hoisted before GRID_SYNC to overlap the predecessor's drain window.
// GEMM/cell bodies identical to the 253us best.
// ---------------------------------------------------------------------------

#define Hc      128
#define MAXBL   32768
#define NGATE   640
#define KB_LEAF 320

__device__ __align__(128) __nv_bfloat16 g_hhiA[MAXBL * Hc];
__device__ __align__(128) __nv_bfloat16 g_hloA[MAXBL * Hc];
__device__ __align__(128) __nv_bfloat16 g_hhiB[(MAXBL / 2) * Hc];
__device__ __align__(128) __nv_bfloat16 g_hloB[(MAXBL / 2) * Hc];
__device__ float g_cA[MAXBL * Hc];
__device__ float g_cB[(MAXBL / 2) * Hc];
__device__ float g_gates[(MAXBL / 2) * NGATE];
__device__ __align__(128) __nv_bfloat16 g_Wt_hi[NGATE * 256];     // [640,256] K-major
__device__ __align__(128) __nv_bfloat16 g_Wt_lo[NGATE * 256];
__device__ float g_Wstf[256 * NGATE];                             // [256,640] fp32
__device__ __align__(128) __nv_bfloat16 g_WlfT_hi[256 * KB_LEAF]; // [256,320]
__device__ __align__(128) __nv_bfloat16 g_WlfT_lo[256 * KB_LEAF];

// ------------------------------- helpers -----------------------------------
#define GRID_SYNC() cudaGridDependencySynchronize()

__device__ __forceinline__ uint32_t smem_u32(const void* p) {
    uint32_t a;
    asm("{ .reg .u64 t; cvta.to.shared.u64 t, %1; cvt.u32.u64 %0, t; }"
        : "=r"(a) : "l"(p));
    return a;
}
#define CP_ASYNC16(dst, src) \
    asm volatile("cp.async.cg.shared.global [%0], [%1], 16;" \
                 :: "r"(dst), "l"(src) : "memory")
#define CP_COMMIT() asm volatile("cp.async.commit_group;" ::: "memory")
#define CP_WAIT1()  asm volatile("cp.async.wait_group 1;"  ::: "memory")
#define CP_WAIT0()  asm volatile("cp.async.wait_group 0;"  ::: "memory")

#define MMA16816(c, a, b)                                                      \
    asm volatile("mma.sync.aligned.m16n8k16.row.col.f32.bf16.bf16.f32 "       \
        "{%0,%1,%2,%3},{%4,%5,%6,%7},{%8,%9},{%0,%1,%2,%3};"                  \
        : "+f"((c)[0]), "+f"((c)[1]), "+f"((c)[2]), "+f"((c)[3])              \
        : "r"((a)[0]), "r"((a)[1]), "r"((a)[2]), "r"((a)[3]),                 \
          "r"((b)[0]), "r"((b)[1]))

__device__ __forceinline__ void ldsm4(uint32_t a, uint32_t& r0, uint32_t& r1,
                                      uint32_t& r2, uint32_t& r3) {
    asm volatile("ldmatrix.sync.aligned.m8n8.x4.shared.b16 {%0,%1,%2,%3}, [%4];"
                 : "=r"(r0), "=r"(r1), "=r"(r2), "=r"(r3) : "r"(a));
}

__device__ __forceinline__ void split_bf16(float w, __nv_bfloat16* hi, __nv_bfloat16* lo) {
    __nv_bfloat16 h = __float2bfloat16(w);
    *hi = h;
    *lo = __float2bfloat16(w - __bfloat162float(h));
}
__device__ __forceinline__ uint32_t pack_bf(__nv_bfloat16 a, __nv_bfloat16 b) {
    __nv_bfloat162 t{a, b};
    return *(uint32_t*)&t;
}
__device__ __forceinline__ float sigf(float x) {
    return __fdividef(1.0f, 1.0f + __expf(-x));
}
__device__ __forceinline__ float tanf_(float x) {
    float t = __expf(2.0f * x);
    return __fdividef(t - 1.0f, t + 1.0f);
}

// Tiles (K-chunk 32, 64B rows): A 64x32 bf16 = 4KB, B 128x32 bf16 = 8KB.
// Stage: A_hi | A_lo | B_hi | B_lo = 24KB. 3 stages = 72KB -> 3 CTAs/SM.
#define TILE_A   4096
#define TILE_Bb  8192
#define STAGE    24576
#define SMEM_REQ (3 * STAGE)

// 64B-row swizzle (verified conflict-free R9).
__device__ __forceinline__ uint32_t sw_off(int row, int chunk) {
    return (uint32_t)(row * 64 + ((chunk ^ ((row >> 1) & 3)) << 4));
}

// ---- compute one 32-K chunk: 2 k-steps; 32x32 warp tile (2x4 warp grid) ----
__device__ __forceinline__ void stage_compute(uint32_t st, int wm, int wn, int lane,
                                              float (*acc)[4][4])
{
    const int ts = lane >> 3, rs = lane & 7;
    const uint32_t Ah = st, Al = st + TILE_A;
    const uint32_t Bh = st + 2 * TILE_A, Bl = st + 2 * TILE_A + TILE_Bb;
    const int arow = wm * 32 + ((ts & 1) << 3) + rs;
    const int ach  = ts >> 1;
    const int brow = wn * 32 + ((ts >> 1) << 3) + rs;
    const int bch  = ts & 1;
    #pragma unroll
    for (int kk = 0; kk < 2; kk++) {
        uint32_t a[2][4], bh[4][2], bl[4][2];
        const int akc = kk * 2 + ach;
        const int bkc = kk * 2 + bch;
        #pragma unroll
        for (int j = 0; j < 2; j++) {
            uint32_t off = sw_off(brow + j * 16, bkc);
            ldsm4(Bh + off, bh[2*j][0], bh[2*j][1], bh[2*j+1][0], bh[2*j+1][1]);
            ldsm4(Bl + off, bl[2*j][0], bl[2*j][1], bl[2*j+1][0], bl[2*j+1][1]);
        }
        #pragma unroll
        for (int am = 0; am < 2; am++) {
            uint32_t off = sw_off(arow + am * 16, akc);
            ldsm4(Ah + off, a[am][0], a[am][1], a[am][2], a[am][3]);
        }
        #pragma unroll
        for (int am = 0; am < 2; am++)
            #pragma unroll
            for (int an = 0; an < 4; an++)
                MMA16816(acc[am][an], a[am], bh[an]);
        #pragma unroll
        for (int am = 0; am < 2; am++)
            #pragma unroll
            for (int an = 0; an < 4; an++)
                MMA16816(acc[am][an], a[am], bl[an]);
        #pragma unroll
        for (int am = 0; am < 2; am++) {
            uint32_t off = sw_off(arow + am * 16, akc);
            ldsm4(Al + off, a[am][0], a[am][1], a[am][2], a[am][3]);
        }
        #pragma unroll
        for (int am = 0; am < 2; am++)
            #pragma unroll
            for (int an = 0; an < 4; an++)
                MMA16816(acc[am][an], a[am], bh[an]);
    }
}

// A-chunk / B-chunk issue (split so weights can prefetch pre-sync).
__device__ __forceinline__ void issueA_lvl(uint32_t sbase, int ch, int tid,
                                           const __nv_bfloat16* Ahi,
                                           const __nv_bfloat16* Alo, int arow0)
{
    uint32_t st = sbase + (uint32_t)(ch % 3) * STAGE;
    #pragma unroll
    for (int i = 0; i < 2; i++) {
        int e = tid + i * 256;                 // 0..511: A hi/lo 64 rows x 4 chunks
        int mat = e >> 8;
        int rem = e & 255;
        int row = rem >> 2, chunk = rem & 3;
        const __nv_bfloat16* src = (mat ? Alo : Ahi)
            + (size_t)(arow0 + row) * 256 + ch * 32 + chunk * 8;
        CP_ASYNC16(st + mat * TILE_A + sw_off(row, chunk), src);
    }
}
__device__ __forceinline__ void issueB_lvl(uint32_t sbase, int ch, int tid,
                                           const __nv_bfloat16* Bhi,
                                           const __nv_bfloat16* Blo, int brow0)
{
    uint32_t st = sbase + (uint32_t)(ch % 3) * STAGE + 2 * TILE_A;
    #pragma unroll
    for (int i = 0; i < 4; i++) {
        int e = tid + i * 256;                 // 0..1023: B hi/lo 128 rows x 4 chunks
        int mat = e >> 9;
        int rem = e & 511;
        int row = rem >> 2, chunk = rem & 3;
        const __nv_bfloat16* src = (mat ? Blo : Bhi)
            + (size_t)(brow0 + row) * 256 + ch * 32 + chunk * 8;
        CP_ASYNC16(st + mat * TILE_Bb + sw_off(row, chunk), src);
    }
}

// ----------------------- merged weight prep (one launch) --------------------
#define WST_ELEMS  (NGATE * 256)
#define WLF_ELEMS  (256 * KB_LEAF)
__global__ void prep_all(const float* __restrict__ Wl, const float* __restrict__ Wr,
                         const float* __restrict__ Wleaf,
                         __nv_bfloat16* __restrict__ whi, __nv_bfloat16* __restrict__ wlo,
                         float* __restrict__ Wf,
                         __nv_bfloat16* __restrict__ lfhi, __nv_bfloat16* __restrict__ lflo)
{
    GRID_SYNC();
    int idx = blockIdx.x * blockDim.x + threadIdx.x;
    if (idx < WST_ELEMS) {
        int n = idx >> 8, k = idx & 255;
        float w = (k < 128) ? Wl[k * NGATE + n] : Wr[(k - 128) * NGATE + n];
        split_bf16(w, &whi[idx], &wlo[idx]);
        Wf[k * NGATE + n] = w;
    } else if (idx < WST_ELEMS + WLF_ELEMS) {
        int j = idx - WST_ELEMS;
        int n = j / KB_LEAF, k = j % KB_LEAF;
        float w = (k < 300) ? Wleaf[k * 256 + n] : 0.0f;
        split_bf16(w, &lfhi[j], &lflo[j]);
    }
}

// ====================== leaf GEMM (R11 config + safe preamble) ==============
__global__ void __launch_bounds__(256, 3)
gemm_leaf(const float* __restrict__ A,
          const __nv_bfloat16* __restrict__ Bhi, const __nv_bfloat16* __restrict__ Blo,
          const float* __restrict__ bias,
          __nv_bfloat16* __restrict__ hhi, __nv_bfloat16* __restrict__ hlo,
          float* __restrict__ cOut, int M, int D)
{
    extern __shared__ char smem[];
    const uint32_t sbase = smem_u32(smem);
    char* const tb = smem;

    const int tid = threadIdx.x;
    const int wid = tid >> 5, lane = tid & 31;
    const int wm = wid >> 2, wn = wid & 3;
    const int g = lane >> 2, t2 = (lane & 3) << 1;
    const int bm = blockIdx.x * 64;
    const int ny = blockIdx.y;
    const int Kc = KB_LEAF / 32;

    float acc[2][4][4];
    #pragma unroll
    for (int i = 0; i < 2; i++)
        #pragma unroll
        for (int j = 0; j < 4; j++)
            #pragma unroll
            for (int q = 0; q < 4; q++) acc[i][j][q] = 0.f;

    float4 aReg[2];

    auto issueB = [&](int ch) {
        uint32_t st = sbase + (uint32_t)(ch % 3) * STAGE + 2 * TILE_A;
        #pragma unroll
        for (int i = 0; i < 4; i++) {
            int e = tid + i * 256;
            int mat = e >> 9;
            int rem = e & 511;
            int row = rem >> 2, chunk = rem & 3;
            const __nv_bfloat16* src = (mat ? Blo : Bhi)
                + (size_t)(ny * 128 + row) * KB_LEAF + ch * 32 + chunk * 8;
            uint32_t dst = st + mat * TILE_Bb + sw_off(row, chunk);
            CP_ASYNC16(dst, src);
        }
    };
    auto ldA = [&](int ch) {
        #pragma unroll
        for (int i = 0; i < 2; i++) {
            int f = tid + i * 256;
            int row = f >> 3, k4 = (f & 7) << 2;
            int k = ch * 32 + k4;
            float4 v = make_float4(0.f, 0.f, 0.f, 0.f);
            if (k < D) v = *(const float4*)(A + (size_t)(bm + row) * D + k);
            aReg[i] = v;
        }
    };
    auto stA = [&](int s) {
        char* st = tb + (s % 3) * STAGE;
        #pragma unroll
        for (int i = 0; i < 2; i++) {
            int f = tid + i * 256;
            int row = f >> 3, k4 = (f & 7) << 2;
            int chunk = k4 >> 3, half = (k4 >> 2) & 1;
            uint32_t off = sw_off(row, chunk) + half * 8;
            float4 v = aReg[i];
            __nv_bfloat16 h0, l0, h1, l1, h2, l2, h3, l3;
            split_bf16(v.x, &h0, &l0); split_bf16(v.y, &h1, &l1);
            split_bf16(v.z, &h2, &l2); split_bf16(v.w, &h3, &l3);
            *(uint2*)(st + off)          = make_uint2(pack_bf(h0, h1), pack_bf(h2, h3));
            *(uint2*)(st + TILE_A + off) = make_uint2(pack_bf(l0, l1), pack_bf(l2, l3));
        }
    };

    // PREAMBLE: x is a harness input (never written on-device) -> safe pre-sync.
    ldA(0);
    stA(0);

    GRID_SYNC();                             // prep_all complete

    issueB(0); CP_COMMIT();
    issueB(1); CP_COMMIT();
    ldA(1);
    for (int ch = 0; ch < Kc; ch++) {
        if (ch + 1 < Kc) CP_WAIT1(); else CP_WAIT0();
        __syncthreads();
        if (ch + 1 < Kc) stA(ch + 1);
        if (ch + 2 < Kc) { issueB(ch + 2); CP_COMMIT(); ldA(ch + 2); }
        stage_compute(sbase + (uint32_t)(ch % 3) * STAGE, wm, wn, lane, acc);
    }

    #pragma unroll
    for (int am = 0; am < 2; am++) {
        int r0 = bm + wm * 32 + am * 16 + g;
        #pragma unroll
        for (int an = 0; an < 4; an++) {
            int c  = wn * 32 + an * 8 + t2;
            float b0 = bias[ny * 128 + c], b1 = bias[ny * 128 + c + 1];
            float v00 = acc[am][an][0] + b0, v01 = acc[am][an][1] + b1;
            float v10 = acc[am][an][2] + b0, v11 = acc[am][an][3] + b1;
            if (ny == 0) {
                __nv_bfloat16 h0, l0, h1, l1;
                split_bf16(v00, &h0, &l0); split_bf16(v01, &h1, &l1);
                *(uint32_t*)(hhi + (size_t)r0 * Hc + c) = pack_bf(h0, h1);
                *(uint32_t*)(hlo + (size_t)r0 * Hc + c) = pack_bf(l0, l1);
                split_bf16(v10, &h0, &l0); split_bf16(v11, &h1, &l1);
                *(uint32_t*)(hhi + (size_t)(r0 + 8) * Hc + c) = pack_bf(h0, h1);
                *(uint32_t*)(hlo + (size_t)(r0 + 8) * Hc + c) = pack_bf(l0, l1);
            } else {
                *(float2*)(cOut + (size_t)r0 * Hc + c)       = make_float2(v00, v01);
                *(float2*)(cOut + (size_t)(r0 + 8) * Hc + c) = make_float2(v10, v11);
            }
        }
    }
}

// ================== level GEMM (weights prefetched pre-sync) ================
__global__ void __launch_bounds__(256, 3)
gemm_level(const __nv_bfloat16* __restrict__ Ahi, const __nv_bfloat16* __restrict__ Alo,
           const __nv_bfloat16* __restrict__ Bhi, const __nv_bfloat16* __restrict__ Blo,
           const float* __restrict__ bias, float* __restrict__ gates, int M)
{
    extern __shared__ char smem[];
    const uint32_t sbase = smem_u32(smem);

    const int tid = threadIdx.x;
    const int wid = tid >> 5, lane = tid & 31;
    const int wm = wid >> 2, wn = wid & 3;
    const int g = lane >> 2, t2 = (lane & 3) << 1;
    const int bm = blockIdx.x * 64;
    const int ny = blockIdx.y;
    const int Kc = 8;

    float acc[2][4][4];
    #pragma unroll
    for (int i = 0; i < 2; i++)
        #pragma unroll
        for (int j = 0; j < 4; j++)
            #pragma unroll
            for (int q = 0; q < 4; q++) acc[i][j][q] = 0.f;

    // PREAMBLE: weights from prep_all (many kernels back) -> safe pre-sync.
    issueB_lvl(sbase, 0, tid, Bhi, Blo, ny * 128);
    issueB_lvl(sbase, 1, tid, Bhi, Blo, ny * 128);

    GRID_SYNC();                             // predecessor cell complete

    issueA_lvl(sbase, 0, tid, Ahi, Alo, bm); CP_COMMIT();   // g0 = B0,B1,A0
    issueA_lvl(sbase, 1, tid, Ahi, Alo, bm); CP_COMMIT();   // g1 = A1
    for (int ch = 0; ch < Kc; ch++) {
        if (ch + 1 < Kc) CP_WAIT1(); else CP_WAIT0();
        __syncthreads();
        if (ch + 2 < Kc) {
            issueA_lvl(sbase, ch + 2, tid, Ahi, Alo, bm);
            issueB_lvl(sbase, ch + 2, tid, Bhi, Blo, ny * 128);
            CP_COMMIT();
        }
        stage_compute(sbase + (uint32_t)(ch % 3) * STAGE, wm, wn, lane, acc);
    }

    #pragma unroll
    for (int am = 0; am < 2; am++) {
        int r0 = bm + wm * 32 + am * 16 + g;
        #pragma unroll
        for (int an = 0; an < 4; an++) {
            int c  = wn * 32 + an * 8 + t2;
            int gc = ny * 128 + c;
            float b0 = bias[gc], b1 = bias[gc + 1];
            *(float2*)(gates + (size_t)r0 * NGATE + gc)
                = make_float2(acc[am][an][0] + b0, acc[am][an][1] + b1);
            *(float2*)(gates + (size_t)(r0 + 8) * NGATE + gc)
                = make_float2(acc[am][an][2] + b0, acc[am][an][3] + b1);
        }
    }
}

// ------------------------------- LSTM cell ----------------------------------
__global__ void lstm_cell4(const float* __restrict__ gates,
                           const float* __restrict__ c_prev,
                           __nv_bfloat16* __restrict__ hhi, __nv_bfloat16* __restrict__ hlo,
                           float* __restrict__ c_out, int M)
{
    int idx = blockIdx.x * blockDim.x + threadIdx.x;
    const bool act = (idx < M * 32);
    int r = idx >> 5, j = (idx & 31) << 2;

    // PREAMBLE: c_prev written by the cell 2 kernels back -> safe pre-sync.
    float4 cl4 = make_float4(0.f, 0.f, 0.f, 0.f), cr4 = cl4;
    if (act) {
        const float* cp = c_prev + (size_t)r * 256;
        cl4 = *(const float4*)(cp + j);
        cr4 = *(const float4*)(cp + 128 + j);
    }

    GRID_SYNC();                             // gates from predecessor GEMM
    if (!act) return;

    const float* g = gates + (size_t)r * NGATE;
    float4 i4  = *(const float4*)(g + j);
    float4 fl4 = *(const float4*)(g + 128 + j);
    float4 fr4 = *(const float4*)(g + 256 + j);
    float4 o4  = *(const float4*)(g + 384 + j);
    float4 g4  = *(const float4*)(g + 512 + j);
    float4 c, h;
#define CEL(X) { float ii = sigf(i4.X), fl = sigf(fl4.X), fr = sigf(fr4.X);      \
                 float oo = sigf(o4.X), gg = tanf_(g4.X);                        \
                 float cc = fl * cl4.X + fr * cr4.X + ii * gg;                   \
                 c.X = cc; h.X = oo * tanf_(cc); }
    CEL(x) CEL(y) CEL(z) CEL(w)
#undef CEL
    *(float4*)(c_out + (size_t)r * Hc + j) = c;
    __nv_bfloat16 b0, l0, b1, l1, b2, l2, b3, l3;
    split_bf16(h.x, &b0, &l0); split_bf16(h.y, &b1, &l1);
    split_bf16(h.z, &b2, &l2); split_bf16(h.w, &b3, &l3);
    *(uint2*)(hhi + (size_t)r * Hc + j) = make_uint2(pack_bf(b0, b1), pack_bf(b2, b3));
    *(uint2*)(hlo + (size_t)r * Hc + j) = make_uint2(pack_bf(l0, l1), pack_bf(l2, l3));
}

// --------------------- fused tiny-level kernel (M <= 128) -------------------
#define RSM 2
__global__ void __launch_bounds__(640)
level_small(const __nv_bfloat16* __restrict__ Ahi, const __nv_bfloat16* __restrict__ Alo,
            const float* __restrict__ Wf, const float* __restrict__ bg,
            const float* __restrict__ c_prev,
            __nv_bfloat16* __restrict__ hhi_o, __nv_bfloat16* __restrict__ hlo_o,
            float* __restrict__ c_out, float* __restrict__ hf_out, int M)
{
    __shared__ float hs[RSM][256];
    __shared__ float gs[RSM][NGATE];
    const int tid = threadIdx.x;
    const int r0 = blockIdx.x * RSM;

    // PREAMBLE: c_prev is 2 kernels back -> safe pre-sync.
    float clp = 0.f, crp = 0.f;
    if (tid < RSM * 128) {
        int r = tid >> 7, u = tid & 127;
        int gr = r0 + r;
        if (gr < M) {
            clp = c_prev[(size_t)gr * 256 + u];
            crp = c_prev[(size_t)gr * 256 + 128 + u];
        }
    }

    GRID_SYNC();                             // h from predecessor ready

    for (int idx = tid; idx < RSM * 256; idx += 640) {
        int r = idx >> 8, k = idx & 255;
        int gr = r0 + r;
        float v = 0.f;
        if (gr < M)
            v = __bfloat162float(Ahi[(size_t)gr * 256 + k])
              + __bfloat162float(Alo[(size_t)gr * 256 + k]);
        hs[r][k] = v;
    }
    __syncthreads();

    {
        const int c = tid;
        float a0 = 0.f, a1 = 0.f;
        #pragma unroll 8
        for (int k = 0; k < 256; k++) {
            float w = Wf[k * NGATE + c];
            a0 += hs[0][k] * w; a1 += hs[1][k] * w;
        }
        float b = bg[c];
        gs[0][c] = a0 + b; gs[1][c] = a1 + b;
    }
    __syncthreads();

    if (tid < RSM * 128) {
        int r = tid >> 7, u = tid & 127;
        int gr = r0 + r;
        if (gr < M) {
            float gi = sigf(gs[r][u]);
            float fl = sigf(gs[r][128 + u]);
            float fr = sigf(gs[r][256 + u]);
            float go = sigf(gs[r][384 + u]);
            float gg = tanf_(gs[r][512 + u]);
            float cc = fl * clp + fr * crp + gi * gg;
            float hh = go * tanf_(cc);
            c_out[(size_t)gr * Hc + u] = cc;
            if (hf_out) {
                hf_out[(size_t)gr * Hc + u] = hh;
            } else {
                __nv_bfloat16 hb, lb;
                split_bf16(hh, &hb, &lb);
                hhi_o[(size_t)gr * Hc + u] = hb;
                hlo_o[(size_t)gr * Hc + u] = lb;
            }
        }
    }
}

// --------------------------- PDL launch helper ------------------------------
static inline void launch_pdl(const void* func, dim3 grid, dim3 block,
                              size_t smem, void** args)
{
    cudaLaunchConfig_t cfg = {};
    cfg.gridDim = grid;
    cfg.blockDim = block;
    cfg.dynamicSmemBytes = smem;
    cfg.stream = 0;
    cudaLaunchAttribute attr[1];
    attr[0].id = cudaLaunchAttributeProgrammaticStreamSerialization;
    attr[0].val.programmaticStreamSerializationAllowed = 1;
    cfg.attrs = attr;
    cfg.numAttrs = 1;
    cudaLaunchKernelExC(&cfg, func, args);
}

// --------------------------------- launch -----------------------------------
extern "C" void kernel_launch(void* const* d_in, const int* in_sizes, int n_in,
                              void* d_out, int out_size)
{
    const float* x      = (const float*)d_in[0];
    const float* W_leaf = (const float*)d_in[1];
    const float* b_leaf = (const float*)d_in[2];
    const float* W_l    = (const float*)d_in[3];
    const float* W_r    = (const float*)d_in[4];
    const float* bg     = (const float*)d_in[5];

    const int twoH = in_sizes[2];            // 256
    const int H    = twoH / 2;               // 128
    const int D    = in_sizes[1] / twoH;     // 300
    const int BL   = in_sizes[0] / D;        // 32768
    const int B    = out_size / H;           // 8
    const int L    = BL / B;                 // 4096
    int levels = 0;
    for (int t = L; t > 1; t >>= 1) levels++;

    __nv_bfloat16 *hhiA, *hloA, *hhiB, *hloB, *Wt_hi, *Wt_lo, *Wlf_hi, *Wlf_lo;
    float *cA, *cB, *gates, *Wstf;
    cudaGetSymbolAddress((void**)&hhiA,   g_hhiA);
    cudaGetSymbolAddress((void**)&hloA,   g_hloA);
    cudaGetSymbolAddress((void**)&hhiB,   g_hhiB);
    cudaGetSymbolAddress((void**)&hloB,   g_hloB);
    cudaGetSymbolAddress((void**)&cA,     g_cA);
    cudaGetSymbolAddress((void**)&cB,     g_cB);
    cudaGetSymbolAddress((void**)&gates,  g_gates);
    cudaGetSymbolAddress((void**)&Wstf,   g_Wstf);
    cudaGetSymbolAddress((void**)&Wt_hi,  g_Wt_hi);
    cudaGetSymbolAddress((void**)&Wt_lo,  g_Wt_lo);
    cudaGetSymbolAddress((void**)&Wlf_hi, g_WlfT_hi);
    cudaGetSymbolAddress((void**)&Wlf_lo, g_WlfT_lo);

    cudaFuncSetAttribute(gemm_leaf,  cudaFuncAttributeMaxDynamicSharedMemorySize, SMEM_REQ);
    cudaFuncSetAttribute(gemm_level, cudaFuncAttributeMaxDynamicSharedMemorySize, SMEM_REQ);

    // 1) merged weight prep
    {
        int total = WST_ELEMS + WLF_ELEMS;
        void* args[] = { (void*)&W_l, (void*)&W_r, (void*)&W_leaf,
                         (void*)&Wt_hi, (void*)&Wt_lo, (void*)&Wstf,
                         (void*)&Wlf_hi, (void*)&Wlf_lo };
        launch_pdl((const void*)prep_all, dim3((total + 255) / 256), dim3(256), 0, args);
    }

    // 2) leaf GEMM
    {
        int M = BL;
        void* args[] = { (void*)&x, (void*)&Wlf_hi, (void*)&Wlf_lo, (void*)&b_leaf,
                         (void*)&hhiA, (void*)&hloA, (void*)&cA, (void*)&M, (void*)&D };
        launch_pdl((const void*)gemm_leaf, dim3(BL / 64, 2), dim3(256), SMEM_REQ, args);
    }

    // 3) reduction levels
    __nv_bfloat16 *sh_hi = hhiA, *sh_lo = hloA, *dh_hi = hhiB, *dh_lo = hloB;
    float *sc = cA, *dc = cB;
    int n = L;
    for (int lvl = 0; lvl < levels; lvl++) {
        n >>= 1;
        int M = B * n;
        bool last = (lvl == levels - 1);

        if (M >= 256) {
            {
                void* args[] = { (void*)&sh_hi, (void*)&sh_lo, (void*)&Wt_hi,
                                 (void*)&Wt_lo, (void*)&bg, (void*)&gates, (void*)&M };
                launch_pdl((const void*)gemm_level, dim3(M / 64, 5), dim3(256),
                           SMEM_REQ, args);
            }
            {
                void* args[] = { (void*)&gates, (void*)&sc, (void*)&dh_hi,
                                 (void*)&dh_lo, (void*)&dc, (void*)&M };
                launch_pdl((const void*)lstm_cell4, dim3((M * 32 + 255) / 256),
                           dim3(256), 0, args);
            }
        } else {
            float* hf = last ? (float*)d_out : nullptr;
            void* args[] = { (void*)&sh_hi, (void*)&sh_lo, (void*)&Wstf, (void*)&bg,
                             (void*)&sc, (void*)&dh_hi, (void*)&dh_lo, (void*)&dc,
                             (void*)&hf, (void*)&M };
            launch_pdl((const void*)level_small, dim3((M + RSM - 1) / RSM),
                       dim3(640), 0, args);
        }

        __nv_bfloat16* t;
        t = sh_hi; sh_hi = dh_hi; dh_hi = t;
        t = sh_lo; sh_lo = dh_lo; dh_lo = t;
        float* tc = sc; sc = dc; dc = tc;
    }
}